// round 6
// baseline (speedup 1.0000x reference)
#include <cuda_runtime.h>
#include <cstdint>
#include <cstddef>

#define NB 4
#define NN 2048
#define CTAB 74                 // CTAs per batch
#define NCTA (NB * CTAB)        // 296 = 2 * 148 SMs exactly
#define TPB 448                 // 14 warps: 7 pair-groups x 2 halves
#define PRG 7
#define CPC 28                  // columns per CTA (last CTA of batch: 4)
#define NITS_K 50
#define TC 4
#define NSTRIPE 8
#define SSTRIDE 64              // 256B between barrier stripes

typedef unsigned long long u64;

constexpr float C_EPS  = 0.1f;
constexpr float C_TOL  = 1e-3f;
constexpr float C_L2E  = 1.4426950408889634f;
constexpr float C_KK   = C_L2E / C_EPS;
constexpr float C_2K   = 2.0f * C_KK;
constexpr float C_INVK = C_EPS / C_L2E;
constexpr float C_LN2  = 0.6931471805599453f;
constexpr float C_AL2E = -2.0f;                  // log2(1/4)

struct ScratchT {
    unsigned barcnt[NSTRIPE * SSTRIDE];     // striped barrier counters
    float AU[NB * NN];
    float BU[NB * NN];
    float errA[2 * NITS_K * NB * 2];        // x2 stripes per (it,b)
    float errB[2 * NITS_K * NB * 2];
    unsigned mvA[2 * NITS_K * NB * 2];
    unsigned mvB[2 * NITS_K * NB * 2];
    float cost[2 * NB];
    float cham[2 * NB];
};
__device__ ScratchT g_s;

__device__ __forceinline__ float ex2f_(float x) {
    float y; asm("ex2.approx.ftz.f32 %0, %1;" : "=f"(y) : "f"(x)); return y;
}
__device__ __forceinline__ float lg2f_(float x) {
    float y; asm("lg2.approx.f32 %0, %1;" : "=f"(y) : "f"(x)); return y;
}
__device__ __forceinline__ u64 pk2(float lo, float hi) {
    u64 r; asm("mov.b64 %0, {%1, %2};" : "=l"(r) : "f"(lo), "f"(hi)); return r;
}
__device__ __forceinline__ void upk(u64 v, float& lo, float& hi) {
    asm("mov.b64 {%0, %1}, %2;" : "=f"(lo), "=f"(hi) : "l"(v));
}
__device__ __forceinline__ u64 pfma(u64 a, u64 b, u64 c) {
    u64 d; asm("fma.rn.f32x2 %0, %1, %2, %3;" : "=l"(d) : "l"(a), "l"(b), "l"(c)); return d;
}
__device__ __forceinline__ u64 padd(u64 a, u64 b) {
    u64 d; asm("add.rn.f32x2 %0, %1, %2;" : "=l"(d) : "l"(a), "l"(b)); return d;
}
__device__ __forceinline__ unsigned encf(float f) {
    unsigned u = __float_as_uint(f);
    return (u & 0x80000000u) ? ~u : (u | 0x80000000u);
}
__device__ __forceinline__ float decf(unsigned e) {
    return (e & 0x80000000u) ? __uint_as_float(e & 0x7fffffffu) : __uint_as_float(~e);
}

// Striped grid barrier: 296 CTAs co-resident (2/SM). Arrivals spread over 8
// counters on distinct L2 lines (~37 same-address REDs instead of 296).
// Spinner sums all 8 (monotonic counters -> stale partial sums are safe).
__device__ __forceinline__ void grid_barrier(unsigned& lb, int stripe) {
    __syncthreads();
    lb++;
    if (threadIdx.x == 0) {
        unsigned target = lb * (unsigned)NCTA;
        asm volatile("red.release.gpu.global.add.u32 [%0], %1;"
                     :: "l"(&g_s.barcnt[stripe * SSTRIDE]), "r"(1u) : "memory");
        unsigned sum;
        do {
            sum = 0;
#pragma unroll
            for (int s = 0; s < NSTRIPE; s++) {
                unsigned v;
                asm volatile("ld.acquire.gpu.global.u32 %0, [%1];"
                             : "=r"(v) : "l"(&g_s.barcnt[s * SSTRIDE]) : "memory");
                sum += v;
            }
        } while (sum < target);
    }
    __syncthreads();
}

// One Sinkhorn half-update, log2 domain, u'-form potentials:
//   stored u'_j = (v_j + alpha)*log2e - k*|q_j|^2
//   v_j = -ln2*(Mv + log2 sum_i 2^(u'_i + 2k r_i.q_j - k|q_j|^2 - Mv))
//   Mv = max_i p_i, p_i = (v_i + alpha)*log2e  (2 striped atomicMax slots)
__device__ void half_update(
    const float* rX, const float* rY, const float* rZ,
    const float* cX, const float* cY, const float* cZ,
    float* sU, float* sPart,
    const float* srcU, float* dstU,
    const unsigned* mvSrc, unsigned* mvDst, float* errSlot,
    bool firstSrc, bool firstDst, int colbase, int es)
{
    const int tid = threadIdx.x;

    if (firstSrc) {
        for (int t = tid; t < NN; t += TPB) {
            float x = rX[t], y = rY[t], z = rZ[t];
            sU[t] = C_AL2E - C_KK * fmaf(x, x, fmaf(y, y, z * z));
        }
    } else {
        for (int t = tid; t < NN; t += TPB) sU[t] = __ldcg(srcU + t);
    }
    // fmaxf ignores NaN from a not-yet-meaningful stripe decode; both stripes
    // are always written (each batch has CTAs of both parities).
    const float Mv = firstSrc ? C_AL2E
                              : fmaxf(decf(__ldcg(mvSrc)), decf(__ldcg(mvSrc + 1)));
    __syncthreads();

    const int wid = tid >> 5, lane = tid & 31;
    const int pr = wid >> 1, h = wid & 1;
    const int j0 = colbase + pr * TC;
    const bool valid = (j0 < NN);

    u64 qx2[TC], qy2[TC], qz2[TC], dj2[TC];
    float qqv[TC], sal[TC], sah[TC];
    if (valid) {
#pragma unroll
        for (int t = 0; t < TC; t++) {
            float qx = cX[j0 + t], qy = cY[j0 + t], qz = cZ[j0 + t];
            float qq = fmaf(qx, qx, fmaf(qy, qy, qz * qz));
            qqv[t] = qq;
            float sx = qx * C_2K, sy = qy * C_2K, sz = qz * C_2K;
            float dj = -C_KK * qq - Mv;
            qx2[t] = pk2(sx, sx); qy2[t] = pk2(sy, sy); qz2[t] = pk2(sz, sz);
            dj2[t] = pk2(dj, dj);
            sal[t] = 0.f; sah[t] = 0.f;
        }

        const float2* pX = (const float2*)rX;
        const float2* pY = (const float2*)rY;
        const float2* pZ = (const float2*)rZ;
        const float2* pU = (const float2*)sU;
        int idx = h * (NN / 4) + lane;
#pragma unroll 4
        for (int k = 0; k < NN / 128; k++, idx += 32) {
            float2 x2 = pX[idx], y2 = pY[idx], z2 = pZ[idx], u2 = pU[idx];
            u64 X2 = pk2(x2.x, x2.y), Y2 = pk2(y2.x, y2.y);
            u64 Z2 = pk2(z2.x, z2.y), U2 = pk2(u2.x, u2.y);
#pragma unroll
            for (int t = 0; t < TC; t++) {
                u64 w = padd(U2, dj2[t]);
                w = pfma(Z2, qz2[t], w);
                w = pfma(Y2, qy2[t], w);
                w = pfma(X2, qx2[t], w);
                float lo, hi; upk(w, lo, hi);
                sal[t] += ex2f_(lo);
                sah[t] += ex2f_(hi);
            }
        }
#pragma unroll
        for (int t = 0; t < TC; t++) sal[t] += sah[t];
#pragma unroll
        for (int o = 16; o > 0; o >>= 1)
#pragma unroll
            for (int t = 0; t < TC; t++)
                sal[t] += __shfl_xor_sync(0xffffffffu, sal[t], o);

        if (h == 1 && lane == 0) {
#pragma unroll
            for (int t = 0; t < TC; t++) sPart[pr * TC + t] = sal[t];
        }
    }
    __syncthreads();

    if (h == 0 && lane == 0) {
        float errsum = 0.f, pmax = -3.4e38f;
        if (valid) {
#pragma unroll
            for (int t = 0; t < TC; t++) {
                float s = fmaxf(sal[t] + sPart[pr * TC + t], 1e-35f);
                float L = Mv + lg2f_(s);
                float pnew = C_AL2E - L;
                float unew = pnew - C_KK * qqv[t];
                float pold = firstDst ? C_AL2E
                                      : (__ldcg(dstU + j0 + t) + C_KK * qqv[t]);
                errsum += fabsf(pnew - pold);
                __stcg(dstU + j0 + t, unew);
                pmax = fmaxf(pmax, pnew);
            }
        }
        sPart[64 + pr] = errsum;
        sPart[72 + pr] = pmax;
    }
    __syncthreads();

    if (tid == 0) {
        float e = 0.f, p = -3.4e38f;
#pragma unroll
        for (int q = 0; q < PRG; q++) {
            e += sPart[64 + q];
            p = fmaxf(p, sPart[72 + q]);
        }
        atomicAdd(errSlot + es, e * C_LN2);     // one same-address atomic per CTA, x2 striped
        atomicMax(mvDst + es, encf(p));
    }
    // trailing sync supplied by caller's grid_barrier
}

// cost = sum_ij exp(A_j + B_i - C_ij/eps) * C_ij (accumulated; /(n*m) at end)
__device__ void cost_pass(
    const float* rX, const float* rY, const float* rZ,
    const float* cX, const float* cY, const float* cZ,
    float* sU, float* sPart,
    const float* srcU, const float* srcColU,
    float* costslot, int colbase)
{
    const int tid = threadIdx.x;
    for (int t = tid; t < NN; t += TPB)
        sU[t] = __ldcg(srcU + t) + 2.0f;     // B*l2e - k|r|^2
    __syncthreads();

    const int wid = tid >> 5, lane = tid & 31;
    const int pr = wid >> 1, h = wid & 1;
    const int j0 = colbase + pr * TC;
    const bool valid = (j0 < NN);

    float a1[TC], a2[TC], qq[TC];
    if (valid) {
        float qx[TC], qy[TC], qz[TC], cp[TC];
#pragma unroll
        for (int t = 0; t < TC; t++) {
            float x = cX[j0 + t], y = cY[j0 + t], z = cZ[j0 + t];
            qq[t] = fmaf(x, x, fmaf(y, y, z * z));
            qx[t] = x * C_2K; qy[t] = y * C_2K; qz[t] = z * C_2K;
            cp[t] = __ldcg(srcColU + j0 + t) + 2.0f;
            a1[t] = 0.f; a2[t] = 0.f;
        }
        const float2* pX = (const float2*)rX;
        const float2* pY = (const float2*)rY;
        const float2* pZ = (const float2*)rZ;
        const float2* pU = (const float2*)sU;
        int idx = h * (NN / 4) + lane;
#pragma unroll 2
        for (int k = 0; k < NN / 128; k++, idx += 32) {
            float2 x2 = pX[idx], y2 = pY[idx], z2 = pZ[idx], u2 = pU[idx];
#pragma unroll
            for (int e = 0; e < 2; e++) {
                float x = e ? x2.y : x2.x, y = e ? y2.y : y2.x;
                float z = e ? z2.y : z2.x, u = e ? u2.y : u2.x;
                float rr = fmaf(x, x, fmaf(y, y, z * z));
#pragma unroll
                for (int t = 0; t < TC; t++) {
                    float w = fmaf(x, qx[t], fmaf(y, qy[t], fmaf(z, qz[t], u)));
                    float ev = ex2f_(w + cp[t]);
                    float Xv = fmaf(u - w, C_INVK, rr);
                    a1[t] = fmaf(ev, Xv, a1[t]);
                    a2[t] += ev;
                }
            }
        }
#pragma unroll
        for (int o = 16; o > 0; o >>= 1)
#pragma unroll
            for (int t = 0; t < TC; t++) {
                a1[t] += __shfl_xor_sync(0xffffffffu, a1[t], o);
                a2[t] += __shfl_xor_sync(0xffffffffu, a2[t], o);
            }
        if (h == 1 && lane == 0) {
#pragma unroll
            for (int t = 0; t < TC; t++) {
                sPart[pr * 8 + t] = a1[t];
                sPart[pr * 8 + 4 + t] = a2[t];
            }
        }
    }
    __syncthreads();
    if (h == 0 && lane == 0) {
        float v = 0.f;
        if (valid) {
#pragma unroll
            for (int t = 0; t < TC; t++) {
                float A1 = a1[t] + sPart[pr * 8 + t];
                float A2 = a2[t] + sPart[pr * 8 + 4 + t];
                v += A1 + qq[t] * A2;
            }
        }
        sPart[64 + pr] = v;
    }
    __syncthreads();
    if (tid == 0) {
        float v = 0.f;
#pragma unroll
        for (int q = 0; q < PRG; q++) v += sPart[64 + q];
        atomicAdd(costslot, v);
    }
    __syncthreads();
}

// chamfer: per own-point j, min over iter-points i of |r_i - q_j|^2
__device__ void cham_pass(
    const float* iX, const float* iY, const float* iZ,
    const float* oX, const float* oY, const float* oZ,
    float* sPart, float* accum, int colbase)
{
    const int tid = threadIdx.x, wid = tid >> 5, lane = tid & 31;
    const int pr = wid >> 1, h = wid & 1;
    const int j0 = colbase + pr * TC;
    const bool valid = (j0 < NN);

    float m[TC], qq[TC];
    if (valid) {
        float qx[TC], qy[TC], qz[TC];
#pragma unroll
        for (int t = 0; t < TC; t++) {
            float x = oX[j0 + t], y = oY[j0 + t], z = oZ[j0 + t];
            qq[t] = fmaf(x, x, fmaf(y, y, z * z));
            qx[t] = -2.f * x; qy[t] = -2.f * y; qz[t] = -2.f * z;
            m[t] = 3.4e38f;
        }
        const float2* pX = (const float2*)iX;
        const float2* pY = (const float2*)iY;
        const float2* pZ = (const float2*)iZ;
        int idx = h * (NN / 4) + lane;
        for (int k = 0; k < NN / 128; k++, idx += 32) {
            float2 x2 = pX[idx], y2 = pY[idx], z2 = pZ[idx];
#pragma unroll
            for (int e = 0; e < 2; e++) {
                float x = e ? x2.y : x2.x, y = e ? y2.y : y2.x, z = e ? z2.y : z2.x;
                float rr = fmaf(x, x, fmaf(y, y, z * z));
#pragma unroll
                for (int t = 0; t < TC; t++) {
                    float v = fmaf(x, qx[t], fmaf(y, qy[t], fmaf(z, qz[t], rr)));
                    m[t] = fminf(m[t], v);
                }
            }
        }
#pragma unroll
        for (int o = 16; o > 0; o >>= 1)
#pragma unroll
            for (int t = 0; t < TC; t++)
                m[t] = fminf(m[t], __shfl_xor_sync(0xffffffffu, m[t], o));
        if (h == 1 && lane == 0) {
#pragma unroll
            for (int t = 0; t < TC; t++) sPart[pr * TC + t] = m[t];
        }
    }
    __syncthreads();
    if (h == 0 && lane == 0) {
        float s = 0.f;
        if (valid) {
#pragma unroll
            for (int t = 0; t < TC; t++)
                s += fminf(m[t], sPart[pr * TC + t]) + qq[t];
        }
        sPart[64 + pr] = s;
    }
    __syncthreads();
    if (tid == 0) {
        float s = 0.f;
#pragma unroll
        for (int q = 0; q < PRG; q++) s += sPart[64 + q];
        atomicAdd(accum, s);
    }
    __syncthreads();
}

__device__ void run_sink(
    const float* rX, const float* rY, const float* rZ,
    const float* cX, const float* cY, const float* cZ,
    float* sU, float* sPart,
    float* AU, float* BU, int off, float* costslot,
    int b, int colbase, int stripe, int es, unsigned& lb)
{
    int it = 0;
    bool cont = true;
    while (cont) {
        const int s2  = (off + it * NB + b) * 2;
        const int s2p = (off + (it == 0 ? 0 : (it - 1)) * NB + b) * 2;
        half_update(rX, rY, rZ, cX, cY, cZ, sU, sPart,
                    BU, AU,
                    &g_s.mvB[s2p], &g_s.mvA[s2], &g_s.errA[s2],
                    it == 0, it == 0, colbase, es);
        grid_barrier(lb, stripe);
        half_update(cX, cY, cZ, rX, rY, rZ, sU, sPart,
                    AU, BU,
                    &g_s.mvA[s2], &g_s.mvB[s2], &g_s.errB[s2],
                    false, it == 0, colbase, es);
        grid_barrier(lb, stripe);
        float ae = 0.f, be = 0.f;
#pragma unroll
        for (int bb = 0; bb < NB; bb++) {
            const int q = (off + it * NB + bb) * 2;
            ae = fmaxf(ae, __ldcg(&g_s.errA[q]) + __ldcg(&g_s.errA[q + 1]));
            be = fmaxf(be, __ldcg(&g_s.errB[q]) + __ldcg(&g_s.errB[q + 1]));
        }
        ae *= (C_EPS / (float)NN);
        be *= (C_EPS / (float)NN);
        it++;
        cont = (it < NITS_K) && (ae >= C_TOL || be >= C_TOL);
    }
    cost_pass(rX, rY, rZ, cX, cY, cZ, sU, sPart, BU, AU, costslot, colbase);
}

__global__ void __launch_bounds__(TPB, 2)
emd_kernel(const float* __restrict__ preds, const float* __restrict__ gts,
           float* __restrict__ out, int out_size)
{
    extern __shared__ float sm[];
    float* sGX = sm;            float* sGY = sm + NN;     float* sGZ = sm + 2 * NN;
    float* sPX = sm + 3 * NN;   float* sPY = sm + 4 * NN; float* sPZ = sm + 5 * NN;
    float* sU  = sm + 6 * NN;
    float* sPart = sm + 7 * NN;   // 128 floats

    const int b       = blockIdx.x / CTAB;
    const int slot    = blockIdx.x % CTAB;
    const int colbase = slot * CPC;
    const int stripe  = blockIdx.x & (NSTRIPE - 1);
    const int es      = slot & 1;            // err/mv stripe

    const float* gp = gts + (size_t)b * NN * 3;
    const float* pp = preds + (size_t)b * NN * 3;
    for (int i = threadIdx.x; i < NN; i += TPB) {
        sGX[i] = gp[3 * i + 0]; sGY[i] = gp[3 * i + 1]; sGZ[i] = gp[3 * i + 2];
        sPX[i] = pp[3 * i + 0]; sPY[i] = pp[3 * i + 1]; sPZ[i] = pp[3 * i + 2];
    }
    __syncthreads();

    unsigned lb = 0;

    cham_pass(sGX, sGY, sGZ, sPX, sPY, sPZ, sPart, &g_s.cham[b], colbase);
    cham_pass(sPX, sPY, sPZ, sGX, sGY, sGZ, sPart, &g_s.cham[NB + b], colbase);

    // run 1: C(gts, preds) — rows = gts (summed in A-half), cols = preds
    run_sink(sGX, sGY, sGZ, sPX, sPY, sPZ, sU, sPart,
             g_s.AU + b * NN, g_s.BU + b * NN, 0, &g_s.cost[b],
             b, colbase, stripe, es, lb);

    // run 2: C(preds, preds)
    run_sink(sPX, sPY, sPZ, sPX, sPY, sPZ, sU, sPart,
             g_s.AU + b * NN, g_s.BU + b * NN, NITS_K * NB, &g_s.cost[NB + b],
             b, colbase, stripe, es, lb);

    grid_barrier(lb, stripe);

    if (blockIdx.x == 0 && threadIdx.x == 0) {
        const float inv_nm = 1.0f / ((float)NN * (float)NN);
        for (int bb = 0; bb < NB && bb < out_size; bb++) {
            float c1 = __ldcg(&g_s.cost[bb]);
            float c2 = __ldcg(&g_s.cost[NB + bb]);
            out[bb] = (c1 - 0.5f * c2) * inv_nm;
        }
        if (out_size >= 5) {
            float ch = 0.f;
            for (int bb = 0; bb < NB; bb++)
                ch += __ldcg(&g_s.cham[bb]) + __ldcg(&g_s.cham[NB + bb]);
            out[4] = ch / (float)(NB * NN);
        }
    }
}

extern "C" void kernel_launch(void* const* d_in, const int* in_sizes, int n_in,
                              void* d_out, int out_size)
{
    const float* preds = (const float*)d_in[0];
    const float* gts   = (const float*)d_in[1];
    float* out = (float*)d_out;

    void* sptr = nullptr;
    cudaGetSymbolAddress(&sptr, g_s);
    cudaMemsetAsync(sptr, 0, sizeof(ScratchT), 0);

    const int smem = (int)((7 * NN + 128) * sizeof(float));
    cudaFuncSetAttribute(emd_kernel, cudaFuncAttributeMaxDynamicSharedMemorySize, smem);
    emd_kernel<<<NCTA, TPB, smem, 0>>>(preds, gts, out, out_size);
}

// round 7
// speedup vs baseline: 1.4269x; 1.4269x over previous
#include <cuda_runtime.h>
#include <cstdint>
#include <cstddef>

#define NB 4
#define NN 2048
#define CTAB 37                 // CTAs per batch
#define NCTA (NB * CTAB)        // 148 = one per SM (register-capped to 1 CTA/SM)
#define TPB 896                 // 28 warps = 7 col-groups x 4 range-splits
#define NGRP 7
#define NSPL 4
#define CPC 56                  // columns per CTA (last CTA of batch: 32)
#define NITS_K 50

typedef unsigned long long u64;

constexpr float C_EPS  = 0.1f;
constexpr float C_TOL  = 1e-3f;
constexpr float C_L2E  = 1.4426950408889634f;
constexpr float C_KK   = C_L2E / C_EPS;          // log2(e)/eps
constexpr float C_2K   = 2.0f * C_KK;
constexpr float C_INVK = C_EPS / C_L2E;
constexpr float C_LN2  = 0.6931471805599453f;
constexpr float C_AL2E = -2.0f;                  // log2(1/4) = alpha*log2(e)

struct ScratchT {
    unsigned barcnt;
    unsigned pad[31];
    float AU[NB * NN];                // u'-form A potentials
    float BU[NB * NN];                // u'-form B potentials
    float errA[2 * NITS_K * NB];
    float errB[2 * NITS_K * NB];
    unsigned mvA[2 * NITS_K * NB];
    unsigned mvB[2 * NITS_K * NB];
    float cost[2 * NB];
    float cham[2 * NB];
};
__device__ ScratchT g_s;

__device__ __forceinline__ float ex2f_(float x) {
    float y; asm("ex2.approx.ftz.f32 %0, %1;" : "=f"(y) : "f"(x)); return y;
}
__device__ __forceinline__ float lg2f_(float x) {
    float y; asm("lg2.approx.f32 %0, %1;" : "=f"(y) : "f"(x)); return y;
}
__device__ __forceinline__ u64 pk2(float lo, float hi) {
    u64 r; asm("mov.b64 %0, {%1, %2};" : "=l"(r) : "f"(lo), "f"(hi)); return r;
}
__device__ __forceinline__ void upk(u64 v, float& lo, float& hi) {
    asm("mov.b64 {%0, %1}, %2;" : "=f"(lo), "=f"(hi) : "l"(v));
}
__device__ __forceinline__ u64 pfma(u64 a, u64 b, u64 c) {
    u64 d; asm("fma.rn.f32x2 %0, %1, %2, %3;" : "=l"(d) : "l"(a), "l"(b), "l"(c)); return d;
}
__device__ __forceinline__ u64 padd(u64 a, u64 b) {
    u64 d; asm("add.rn.f32x2 %0, %1, %2;" : "=l"(d) : "l"(a), "l"(b)); return d;
}
__device__ __forceinline__ unsigned encf(float f) {
    unsigned u = __float_as_uint(f);
    return (u & 0x80000000u) ? ~u : (u | 0x80000000u);
}
__device__ __forceinline__ float decf(unsigned e) {
    return (e & 0x80000000u) ? __uint_as_float(e & 0x7fffffffu) : __uint_as_float(~e);
}

// grid barrier: 148 CTAs, exactly one per SM (register-limited). Single
// monotonic counter, release-RED arrive, acquire-LD hot spin.
__device__ __forceinline__ void grid_barrier(unsigned& lb) {
    __syncthreads();
    lb++;
    if (threadIdx.x == 0) {
        unsigned target = lb * (unsigned)NCTA;
        asm volatile("red.release.gpu.global.add.u32 [%0], %1;"
                     :: "l"(&g_s.barcnt), "r"(1u) : "memory");
        unsigned v;
        do {
            asm volatile("ld.acquire.gpu.global.u32 %0, [%1];"
                         : "=r"(v) : "l"(&g_s.barcnt) : "memory");
        } while (v < target);
    }
    __syncthreads();
}

// One Sinkhorn half-update, log2 domain, u'-form potentials:
//   stored u'_j = (v_j + alpha)*log2e - k*|q_j|^2
//   v_j = -ln2*(Mv + log2 sum_i 2^(u'_i + 2k r_i.q_j - k|q_j|^2 - Mv))
//   Mv = max_i p_i,  p_i = (v_i + alpha)*log2e
// Column-packed f32x2: each warp handles 8 columns (4 packed pairs) over a
// quarter of the i-range; partials folded across splits via smem.
__device__ void half_update(
    const float2* rXY, const float* rZ,      // summed cloud
    const float2* cXY, const float* cZ,      // output cloud
    float2* sZU, float* sPart,
    const float* srcU, float* dstU,
    const unsigned* mvSrc, unsigned* mvDst, float* errSlot,
    bool firstSrc, bool firstDst, int colbase)
{
    const int tid = threadIdx.x;

    // phase 1: rebuild (z, u') for the summed cloud
    if (firstSrc) {
        for (int t = tid; t < NN; t += TPB) {
            float2 xy = rXY[t]; float z = rZ[t];
            float u = C_AL2E - C_KK * fmaf(xy.x, xy.x, fmaf(xy.y, xy.y, z * z));
            sZU[t] = make_float2(z, u);
        }
    } else {
        for (int t = tid; t < NN; t += TPB)
            sZU[t] = make_float2(rZ[t], __ldcg(srcU + t));
    }
    const float Mv = firstSrc ? C_AL2E : decf(__ldcg(mvSrc));
    __syncthreads();

    const int w = tid >> 5, lane = tid & 31;
    const int grp = w >> 2, split = w & 3;
    const int j0 = colbase + grp * 8;
    const bool valid = (j0 < NN);

    if (valid) {
        u64 qx2[4], qy2[4], qz2[4], dj2[4];
        float sal[8];
#pragma unroll
        for (int p = 0; p < 4; p++) {
            float2 qa = cXY[j0 + 2 * p], qb = cXY[j0 + 2 * p + 1];
            float za = cZ[j0 + 2 * p], zb = cZ[j0 + 2 * p + 1];
            float qqa = fmaf(qa.x, qa.x, fmaf(qa.y, qa.y, za * za));
            float qqb = fmaf(qb.x, qb.x, fmaf(qb.y, qb.y, zb * zb));
            qx2[p] = pk2(qa.x * C_2K, qb.x * C_2K);
            qy2[p] = pk2(qa.y * C_2K, qb.y * C_2K);
            qz2[p] = pk2(za * C_2K, zb * C_2K);
            dj2[p] = pk2(-C_KK * qqa - Mv, -C_KK * qqb - Mv);
            sal[2 * p] = 0.f; sal[2 * p + 1] = 0.f;
        }

        int idx = split * (NN / NSPL) + lane;
#pragma unroll 4
        for (int k = 0; k < NN / NSPL / 32; k++, idx += 32) {
            float2 xy = rXY[idx];
            float2 zu = sZU[idx];
            u64 X2 = pk2(xy.x, xy.x), Y2 = pk2(xy.y, xy.y);
            u64 Z2 = pk2(zu.x, zu.x), U2 = pk2(zu.y, zu.y);
#pragma unroll
            for (int p = 0; p < 4; p++) {
                u64 t0 = padd(U2, dj2[p]);
                t0 = pfma(Z2, qz2[p], t0);
                t0 = pfma(Y2, qy2[p], t0);
                t0 = pfma(X2, qx2[p], t0);
                float lo, hi; upk(t0, lo, hi);
                sal[2 * p]     += ex2f_(lo);
                sal[2 * p + 1] += ex2f_(hi);
            }
        }
#pragma unroll
        for (int o = 16; o > 0; o >>= 1)
#pragma unroll
            for (int c = 0; c < 8; c++)
                sal[c] += __shfl_xor_sync(0xffffffffu, sal[c], o);
        if (lane == 0) {
#pragma unroll
            for (int c = 0; c < 8; c++)
                sPart[grp * 32 + split * 8 + c] = sal[c];
        }
    }
    __syncthreads();

    // epilogue: split-0 warps, lanes 0..7 each own one column
    if (valid && split == 0) {
        float e = 0.f, pm = -3.4e38f;
        if (lane < 8) {
            float s = sPart[grp * 32 + lane] + sPart[grp * 32 + 8 + lane]
                    + sPart[grp * 32 + 16 + lane] + sPart[grp * 32 + 24 + lane];
            s = fmaxf(s, 1e-35f);
            float L = Mv + lg2f_(s);
            float pnew = C_AL2E - L;
            float2 q = cXY[j0 + lane]; float z = cZ[j0 + lane];
            float qq = fmaf(q.x, q.x, fmaf(q.y, q.y, z * z));
            float unew = pnew - C_KK * qq;
            float pold = firstDst ? C_AL2E
                                  : (__ldcg(dstU + j0 + lane) + C_KK * qq);
            e = fabsf(pnew - pold);
            pm = pnew;
            __stcg(dstU + j0 + lane, unew);
        }
#pragma unroll
        for (int o = 16; o > 0; o >>= 1) {
            e += __shfl_xor_sync(0xffffffffu, e, o);
            pm = fmaxf(pm, __shfl_xor_sync(0xffffffffu, pm, o));
        }
        if (lane == 0) {
            atomicAdd(errSlot, e * C_LN2);
            atomicMax(mvDst, encf(pm));
        }
    }
    // trailing sync supplied by caller's grid_barrier
}

// cost = sum_ij exp(A_j + B_i - C_ij/eps) * C_ij (accumulated; /(n*m) at end)
// Runs once per Sinkhorn run; scalar math, 2 chunks of 4 cols to bound regs.
__device__ void cost_pass(
    const float2* rXY, const float* rZ,
    const float2* cXY, const float* cZ,
    float2* sZU, float* sPart,
    const float* srcU, const float* srcColU,
    float* costslot, int colbase)
{
    const int tid = threadIdx.x;
    for (int t = tid; t < NN; t += TPB)
        sZU[t] = make_float2(rZ[t], __ldcg(srcU + t) + 2.0f);   // B*l2e - k|r|^2
    __syncthreads();

    const int w = tid >> 5, lane = tid & 31;
    const int grp = w >> 2, split = w & 3;
    const int j0 = colbase + grp * 8;
    const bool valid = (j0 < NN);

    float v = 0.f;
    if (valid) {
        for (int ch = 0; ch < 2; ch++) {
            const int jb = j0 + ch * 4;
            float qx[4], qy[4], qz[4], cp[4], qq[4], a1[4], a2[4];
#pragma unroll
            for (int t = 0; t < 4; t++) {
                float2 q = cXY[jb + t]; float z = cZ[jb + t];
                qq[t] = fmaf(q.x, q.x, fmaf(q.y, q.y, z * z));
                qx[t] = q.x * C_2K; qy[t] = q.y * C_2K; qz[t] = z * C_2K;
                cp[t] = __ldcg(srcColU + jb + t) + 2.0f;   // A*l2e - k|q|^2
                a1[t] = 0.f; a2[t] = 0.f;
            }
            int idx = split * (NN / NSPL) + lane;
#pragma unroll 2
            for (int k = 0; k < NN / NSPL / 32; k++, idx += 32) {
                float2 xy = rXY[idx];
                float2 zu = sZU[idx];
                float x = xy.x, y = xy.y, z = zu.x, u = zu.y;
                float rr = fmaf(x, x, fmaf(y, y, z * z));
#pragma unroll
                for (int t = 0; t < 4; t++) {
                    float ww = fmaf(x, qx[t], fmaf(y, qy[t], fmaf(z, qz[t], u)));
                    float ev = ex2f_(ww + cp[t]);
                    float Xv = fmaf(u - ww, C_INVK, rr);    // |r|^2 - 2 r.q
                    a1[t] = fmaf(ev, Xv, a1[t]);
                    a2[t] += ev;
                }
            }
#pragma unroll
            for (int t = 0; t < 4; t++) v += a1[t] + qq[t] * a2[t];
        }
    }
#pragma unroll
    for (int o = 16; o > 0; o >>= 1)
        v += __shfl_xor_sync(0xffffffffu, v, o);
    if (lane == 0) sPart[w] = v;
    __syncthreads();
    if (tid == 0) {
        float s = 0.f;
#pragma unroll
        for (int q = 0; q < TPB / 32; q++) s += sPart[q];
        atomicAdd(costslot, s);
    }
    __syncthreads();
}

// chamfer: per own-point j, min over iter-points i of |r_i - q_j|^2
__device__ void cham_pass(
    const float2* iXY, const float* iZ,
    const float2* oXY, const float* oZ,
    float* sPart, float* accum, int colbase)
{
    const int tid = threadIdx.x, w = tid >> 5, lane = tid & 31;
    const int grp = w >> 2, split = w & 3;
    const int j0 = colbase + grp * 8;
    const bool valid = (j0 < NN);

    if (valid) {
        for (int ch = 0; ch < 2; ch++) {
            const int jb = j0 + ch * 4;
            float qx[4], qy[4], qz[4], m[4];
#pragma unroll
            for (int t = 0; t < 4; t++) {
                float2 q = oXY[jb + t]; float z = oZ[jb + t];
                qx[t] = -2.f * q.x; qy[t] = -2.f * q.y; qz[t] = -2.f * z;
                m[t] = 3.4e38f;
            }
            int idx = split * (NN / NSPL) + lane;
            for (int k = 0; k < NN / NSPL / 32; k++, idx += 32) {
                float2 xy = iXY[idx]; float z = iZ[idx];
                float rr = fmaf(xy.x, xy.x, fmaf(xy.y, xy.y, z * z));
#pragma unroll
                for (int t = 0; t < 4; t++) {
                    float vv = fmaf(xy.x, qx[t], fmaf(xy.y, qy[t], fmaf(z, qz[t], rr)));
                    m[t] = fminf(m[t], vv);
                }
            }
#pragma unroll
            for (int o = 16; o > 0; o >>= 1)
#pragma unroll
                for (int t = 0; t < 4; t++)
                    m[t] = fminf(m[t], __shfl_xor_sync(0xffffffffu, m[t], o));
            if (lane == 0) {
#pragma unroll
                for (int t = 0; t < 4; t++)
                    sPart[grp * 32 + split * 8 + ch * 4 + t] = m[t];
            }
        }
    }
    __syncthreads();
    // fold splits, add |q|^2, per-group sum
    if (valid && split == 0) {
        float s = 0.f;
        if (lane < 8) {
            float mm = fminf(fminf(sPart[grp * 32 + lane], sPart[grp * 32 + 8 + lane]),
                             fminf(sPart[grp * 32 + 16 + lane], sPart[grp * 32 + 24 + lane]));
            float2 q = oXY[j0 + lane]; float z = oZ[j0 + lane];
            s = mm + fmaf(q.x, q.x, fmaf(q.y, q.y, z * z));
        }
#pragma unroll
        for (int o = 16; o > 0; o >>= 1)
            s += __shfl_xor_sync(0xffffffffu, s, o);
        if (lane == 0) atomicAdd(accum, s);
    }
    __syncthreads();
}

__device__ void run_sink(
    const float2* rXY, const float* rZ,
    const float2* cXY, const float* cZ,
    float2* sZU, float* sPart,
    float* AU, float* BU, int off, float* costslot, int b, int colbase, unsigned& lb)
{
    int it = 0;
    bool cont = true;
    while (cont) {
        half_update(rXY, rZ, cXY, cZ, sZU, sPart,
                    BU, AU,
                    &g_s.mvB[off + (it == 0 ? 0 : (it - 1) * NB) + b],
                    &g_s.mvA[off + it * NB + b],
                    &g_s.errA[off + it * NB + b],
                    it == 0, it == 0, colbase);
        grid_barrier(lb);
        half_update(cXY, cZ, rXY, rZ, sZU, sPart,
                    AU, BU,
                    &g_s.mvA[off + it * NB + b],
                    &g_s.mvB[off + it * NB + b],
                    &g_s.errB[off + it * NB + b],
                    false, it == 0, colbase);
        grid_barrier(lb);
        float ae = 0.f, be = 0.f;
#pragma unroll
        for (int bb = 0; bb < NB; bb++) {
            ae = fmaxf(ae, __ldcg(&g_s.errA[off + it * NB + bb]));
            be = fmaxf(be, __ldcg(&g_s.errB[off + it * NB + bb]));
        }
        ae *= (C_EPS / (float)NN);
        be *= (C_EPS / (float)NN);
        it++;
        cont = (it < NITS_K) && (ae >= C_TOL || be >= C_TOL);
    }
    cost_pass(rXY, rZ, cXY, cZ, sZU, sPart, BU, AU, costslot, colbase);
}

__global__ void __launch_bounds__(TPB, 1)
emd_kernel(const float* __restrict__ preds, const float* __restrict__ gts,
           float* __restrict__ out, int out_size)
{
    extern __shared__ float sm[];
    float2* sGXY = (float2*)sm;                       // 2048 float2
    float2* sPXY = (float2*)(sm + 2 * NN);
    float*  sGZ  = sm + 4 * NN;
    float*  sPZ  = sm + 5 * NN;
    float2* sZU  = (float2*)(sm + 6 * NN);            // (z, u') rebuilt per half
    float*  sPart = sm + 8 * NN;                      // 256 floats

    const int b       = blockIdx.x / CTAB;
    const int slot    = blockIdx.x % CTAB;
    const int colbase = slot * CPC;

    const float* gp = gts + (size_t)b * NN * 3;
    const float* pp = preds + (size_t)b * NN * 3;
    for (int i = threadIdx.x; i < NN; i += TPB) {
        sGXY[i] = make_float2(gp[3 * i + 0], gp[3 * i + 1]);
        sGZ[i]  = gp[3 * i + 2];
        sPXY[i] = make_float2(pp[3 * i + 0], pp[3 * i + 1]);
        sPZ[i]  = pp[3 * i + 2];
    }
    __syncthreads();

    unsigned lb = 0;

    cham_pass(sGXY, sGZ, sPXY, sPZ, sPart, &g_s.cham[b], colbase);
    cham_pass(sPXY, sPZ, sGXY, sGZ, sPart, &g_s.cham[NB + b], colbase);

    // run 1: C(gts, preds) — rows = gts (summed in A-half), cols = preds
    run_sink(sGXY, sGZ, sPXY, sPZ, sZU, sPart,
             g_s.AU + b * NN, g_s.BU + b * NN, 0, &g_s.cost[b], b, colbase, lb);

    // run 2: C(preds, preds)
    run_sink(sPXY, sPZ, sPXY, sPZ, sZU, sPart,
             g_s.AU + b * NN, g_s.BU + b * NN, NITS_K * NB, &g_s.cost[NB + b],
             b, colbase, lb);

    grid_barrier(lb);

    if (blockIdx.x == 0 && threadIdx.x == 0) {
        const float inv_nm = 1.0f / ((float)NN * (float)NN);
        for (int bb = 0; bb < NB && bb < out_size; bb++) {
            float c1 = __ldcg(&g_s.cost[bb]);
            float c2 = __ldcg(&g_s.cost[NB + bb]);
            out[bb] = (c1 - 0.5f * c2) * inv_nm;
        }
        if (out_size >= 5) {
            float ch = 0.f;
            for (int bb = 0; bb < NB; bb++)
                ch += __ldcg(&g_s.cham[bb]) + __ldcg(&g_s.cham[NB + bb]);
            out[4] = ch / (float)(NB * NN);
        }
    }
}

extern "C" void kernel_launch(void* const* d_in, const int* in_sizes, int n_in,
                              void* d_out, int out_size)
{
    const float* preds = (const float*)d_in[0];
    const float* gts   = (const float*)d_in[1];
    float* out = (float*)d_out;

    void* sptr = nullptr;
    cudaGetSymbolAddress(&sptr, g_s);
    cudaMemsetAsync(sptr, 0, sizeof(ScratchT), 0);

    const int smem = (int)((8 * NN + 256) * sizeof(float));
    cudaFuncSetAttribute(emd_kernel, cudaFuncAttributeMaxDynamicSharedMemorySize, smem);
    emd_kernel<<<NCTA, TPB, smem, 0>>>(preds, gts, out, out_size);
}

// round 8
// speedup vs baseline: 1.6727x; 1.1723x over previous
#include <cuda_runtime.h>
#include <cstdint>
#include <cstddef>

#define NB 4
#define NN 2048
#define CTAB 37                 // CTAs per batch
#define NCTA (NB * CTAB)        // 148 = one per SM
#define TPB 896                 // 28 warps = 7 col-groups x 4 range-splits
#define NSPL 4
#define CPC 56                  // columns per CTA (last CTA of batch: 32)
#define NITS_K 50

typedef unsigned long long u64;

constexpr float C_EPS  = 0.1f;
constexpr float C_TOL  = 1e-3f;
constexpr float C_L2E  = 1.4426950408889634f;
constexpr float C_KK   = C_L2E / C_EPS;
constexpr float C_2K   = 2.0f * C_KK;
constexpr float C_INVK = C_EPS / C_L2E;
constexpr float C_LN2  = 0.6931471805599453f;
constexpr float C_AL2E = -2.0f;                  // log2(1/4)

struct ScratchT {
    unsigned barcnt;
    unsigned pad[31];
    float AU1[NB * NN];
    float BU1[NB * NN];
    float AU2[NB * NN];
    float BU2[NB * NN];
    float errA[2 * NITS_K * NB];
    float errB[2 * NITS_K * NB];
    unsigned mvA[2 * NITS_K * NB];
    unsigned mvB[2 * NITS_K * NB];
    float cost[2 * NB];
    float cham[2 * NB];
};
__device__ ScratchT g_s;

__device__ __forceinline__ float ex2f_(float x) {
    float y; asm("ex2.approx.ftz.f32 %0, %1;" : "=f"(y) : "f"(x)); return y;
}
__device__ __forceinline__ float lg2f_(float x) {
    float y; asm("lg2.approx.f32 %0, %1;" : "=f"(y) : "f"(x)); return y;
}
__device__ __forceinline__ u64 pk2(float lo, float hi) {
    u64 r; asm("mov.b64 %0, {%1, %2};" : "=l"(r) : "f"(lo), "f"(hi)); return r;
}
__device__ __forceinline__ void upk(u64 v, float& lo, float& hi) {
    asm("mov.b64 {%0, %1}, %2;" : "=f"(lo), "=f"(hi) : "l"(v));
}
__device__ __forceinline__ u64 pfma(u64 a, u64 b, u64 c) {
    u64 d; asm("fma.rn.f32x2 %0, %1, %2, %3;" : "=l"(d) : "l"(a), "l"(b), "l"(c)); return d;
}
__device__ __forceinline__ u64 padd(u64 a, u64 b) {
    u64 d; asm("add.rn.f32x2 %0, %1, %2;" : "=l"(d) : "l"(a), "l"(b)); return d;
}
__device__ __forceinline__ unsigned encf(float f) {
    unsigned u = __float_as_uint(f);
    return (u & 0x80000000u) ? ~u : (u | 0x80000000u);
}
__device__ __forceinline__ float decf(unsigned e) {
    return (e & 0x80000000u) ? __uint_as_float(e & 0x7fffffffu) : __uint_as_float(~e);
}

// grid barrier: 148 CTAs, one per SM. Single monotonic counter.
__device__ __forceinline__ void grid_barrier(unsigned& lb) {
    __syncthreads();
    lb++;
    if (threadIdx.x == 0) {
        unsigned target = lb * (unsigned)NCTA;
        asm volatile("red.release.gpu.global.add.u32 [%0], %1;"
                     :: "l"(&g_s.barcnt), "r"(1u) : "memory");
        unsigned v;
        do {
            asm volatile("ld.acquire.gpu.global.u32 %0, [%1];"
                         : "=r"(v) : "l"(&g_s.barcnt) : "memory");
        } while (v < target);
    }
    __syncthreads();
}

// One Sinkhorn half-update, log2 domain, u'-form potentials (see R7).
__device__ void half_update(
    const float2* rXY, const float* rZ,
    const float2* cXY, const float* cZ,
    float2* sZU, float* sPart,
    const float* srcU, float* dstU,
    const unsigned* mvSrc, unsigned* mvDst, float* errSlot,
    bool firstSrc, bool firstDst, int colbase)
{
    const int tid = threadIdx.x;

    if (firstSrc) {
        for (int t = tid; t < NN; t += TPB) {
            float2 xy = rXY[t]; float z = rZ[t];
            float u = C_AL2E - C_KK * fmaf(xy.x, xy.x, fmaf(xy.y, xy.y, z * z));
            sZU[t] = make_float2(z, u);
        }
    } else {
        for (int t = tid; t < NN; t += TPB)
            sZU[t] = make_float2(rZ[t], __ldcg(srcU + t));
    }
    const float Mv = firstSrc ? C_AL2E : decf(__ldcg(mvSrc));
    __syncthreads();

    const int w = tid >> 5, lane = tid & 31;
    const int grp = w >> 2, split = w & 3;
    const int j0 = colbase + grp * 8;
    const bool valid = (j0 < NN);

    if (valid) {
        u64 qx2[4], qy2[4], qz2[4], dj2[4];
        float sal[8];
#pragma unroll
        for (int p = 0; p < 4; p++) {
            float2 qa = cXY[j0 + 2 * p], qb = cXY[j0 + 2 * p + 1];
            float za = cZ[j0 + 2 * p], zb = cZ[j0 + 2 * p + 1];
            float qqa = fmaf(qa.x, qa.x, fmaf(qa.y, qa.y, za * za));
            float qqb = fmaf(qb.x, qb.x, fmaf(qb.y, qb.y, zb * zb));
            qx2[p] = pk2(qa.x * C_2K, qb.x * C_2K);
            qy2[p] = pk2(qa.y * C_2K, qb.y * C_2K);
            qz2[p] = pk2(za * C_2K, zb * C_2K);
            dj2[p] = pk2(-C_KK * qqa - Mv, -C_KK * qqb - Mv);
            sal[2 * p] = 0.f; sal[2 * p + 1] = 0.f;
        }

        int idx = split * (NN / NSPL) + lane;
#pragma unroll 4
        for (int k = 0; k < NN / NSPL / 32; k++, idx += 32) {
            float2 xy = rXY[idx];
            float2 zu = sZU[idx];
            u64 X2 = pk2(xy.x, xy.x), Y2 = pk2(xy.y, xy.y);
            u64 Z2 = pk2(zu.x, zu.x), U2 = pk2(zu.y, zu.y);
#pragma unroll
            for (int p = 0; p < 4; p++) {
                u64 t0 = padd(U2, dj2[p]);
                t0 = pfma(Z2, qz2[p], t0);
                t0 = pfma(Y2, qy2[p], t0);
                t0 = pfma(X2, qx2[p], t0);
                float lo, hi; upk(t0, lo, hi);
                sal[2 * p]     += ex2f_(lo);
                sal[2 * p + 1] += ex2f_(hi);
            }
        }
#pragma unroll
        for (int o = 16; o > 0; o >>= 1)
#pragma unroll
            for (int c = 0; c < 8; c++)
                sal[c] += __shfl_xor_sync(0xffffffffu, sal[c], o);
        if (lane == 0) {
#pragma unroll
            for (int c = 0; c < 8; c++)
                sPart[grp * 32 + split * 8 + c] = sal[c];
        }
    }
    __syncthreads();

    if (valid && split == 0) {
        float e = 0.f, pm = -3.4e38f;
        if (lane < 8) {
            float s = sPart[grp * 32 + lane] + sPart[grp * 32 + 8 + lane]
                    + sPart[grp * 32 + 16 + lane] + sPart[grp * 32 + 24 + lane];
            s = fmaxf(s, 1e-35f);
            float L = Mv + lg2f_(s);
            float pnew = C_AL2E - L;
            float2 q = cXY[j0 + lane]; float z = cZ[j0 + lane];
            float qq = fmaf(q.x, q.x, fmaf(q.y, q.y, z * z));
            float unew = pnew - C_KK * qq;
            float pold = firstDst ? C_AL2E
                                  : (__ldcg(dstU + j0 + lane) + C_KK * qq);
            e = fabsf(pnew - pold);
            pm = pnew;
            __stcg(dstU + j0 + lane, unew);
        }
#pragma unroll
        for (int o = 16; o > 0; o >>= 1) {
            e += __shfl_xor_sync(0xffffffffu, e, o);
            pm = fmaxf(pm, __shfl_xor_sync(0xffffffffu, pm, o));
        }
        if (lane == 0) {
            atomicAdd(errSlot, e * C_LN2);
            atomicMax(mvDst, encf(pm));
        }
    }
    __syncthreads();
}

// cost = sum_ij exp(A_j + B_i - C_ij/eps) * C_ij (accumulated; /(n*m) at end)
__device__ void cost_pass(
    const float2* rXY, const float* rZ,
    const float2* cXY, const float* cZ,
    float2* sZU, float* sPart,
    const float* srcU, const float* srcColU,
    float* costslot, int colbase)
{
    const int tid = threadIdx.x;
    for (int t = tid; t < NN; t += TPB)
        sZU[t] = make_float2(rZ[t], __ldcg(srcU + t) + 2.0f);
    __syncthreads();

    const int w = tid >> 5, lane = tid & 31;
    const int grp = w >> 2, split = w & 3;
    const int j0 = colbase + grp * 8;
    const bool valid = (j0 < NN);

    float v = 0.f;
    if (valid) {
        for (int ch = 0; ch < 2; ch++) {
            const int jb = j0 + ch * 4;
            float qx[4], qy[4], qz[4], cp[4], qq[4], a1[4], a2[4];
#pragma unroll
            for (int t = 0; t < 4; t++) {
                float2 q = cXY[jb + t]; float z = cZ[jb + t];
                qq[t] = fmaf(q.x, q.x, fmaf(q.y, q.y, z * z));
                qx[t] = q.x * C_2K; qy[t] = q.y * C_2K; qz[t] = z * C_2K;
                cp[t] = __ldcg(srcColU + jb + t) + 2.0f;
                a1[t] = 0.f; a2[t] = 0.f;
            }
            int idx = split * (NN / NSPL) + lane;
#pragma unroll 2
            for (int k = 0; k < NN / NSPL / 32; k++, idx += 32) {
                float2 xy = rXY[idx];
                float2 zu = sZU[idx];
                float x = xy.x, y = xy.y, z = zu.x, u = zu.y;
                float rr = fmaf(x, x, fmaf(y, y, z * z));
#pragma unroll
                for (int t = 0; t < 4; t++) {
                    float ww = fmaf(x, qx[t], fmaf(y, qy[t], fmaf(z, qz[t], u)));
                    float ev = ex2f_(ww + cp[t]);
                    float Xv = fmaf(u - ww, C_INVK, rr);
                    a1[t] = fmaf(ev, Xv, a1[t]);
                    a2[t] += ev;
                }
            }
#pragma unroll
            for (int t = 0; t < 4; t++) v += a1[t] + qq[t] * a2[t];
        }
    }
#pragma unroll
    for (int o = 16; o > 0; o >>= 1)
        v += __shfl_xor_sync(0xffffffffu, v, o);
    if (lane == 0) sPart[w] = v;
    __syncthreads();
    if (tid == 0) {
        float s = 0.f;
#pragma unroll
        for (int q = 0; q < TPB / 32; q++) s += sPart[q];
        atomicAdd(costslot, s);
    }
    __syncthreads();
}

// chamfer: per own-point j, min over iter-points i of |r_i - q_j|^2
__device__ void cham_pass(
    const float2* iXY, const float* iZ,
    const float2* oXY, const float* oZ,
    float* sPart, float* accum, int colbase)
{
    const int tid = threadIdx.x, w = tid >> 5, lane = tid & 31;
    const int grp = w >> 2, split = w & 3;
    const int j0 = colbase + grp * 8;
    const bool valid = (j0 < NN);

    if (valid) {
        for (int ch = 0; ch < 2; ch++) {
            const int jb = j0 + ch * 4;
            float qx[4], qy[4], qz[4], m[4];
#pragma unroll
            for (int t = 0; t < 4; t++) {
                float2 q = oXY[jb + t]; float z = oZ[jb + t];
                qx[t] = -2.f * q.x; qy[t] = -2.f * q.y; qz[t] = -2.f * z;
                m[t] = 3.4e38f;
            }
            int idx = split * (NN / NSPL) + lane;
            for (int k = 0; k < NN / NSPL / 32; k++, idx += 32) {
                float2 xy = iXY[idx]; float z = iZ[idx];
                float rr = fmaf(xy.x, xy.x, fmaf(xy.y, xy.y, z * z));
#pragma unroll
                for (int t = 0; t < 4; t++) {
                    float vv = fmaf(xy.x, qx[t], fmaf(xy.y, qy[t], fmaf(z, qz[t], rr)));
                    m[t] = fminf(m[t], vv);
                }
            }
#pragma unroll
            for (int o = 16; o > 0; o >>= 1)
#pragma unroll
                for (int t = 0; t < 4; t++)
                    m[t] = fminf(m[t], __shfl_xor_sync(0xffffffffu, m[t], o));
            if (lane == 0) {
#pragma unroll
                for (int t = 0; t < 4; t++)
                    sPart[grp * 32 + split * 8 + ch * 4 + t] = m[t];
            }
        }
    }
    __syncthreads();
    if (valid && split == 0) {
        float s = 0.f;
        if (lane < 8) {
            float mm = fminf(fminf(sPart[grp * 32 + lane], sPart[grp * 32 + 8 + lane]),
                             fminf(sPart[grp * 32 + 16 + lane], sPart[grp * 32 + 24 + lane]));
            float2 q = oXY[j0 + lane]; float z = oZ[j0 + lane];
            s = mm + fmaf(q.x, q.x, fmaf(q.y, q.y, z * z));
        }
#pragma unroll
        for (int o = 16; o > 0; o >>= 1)
            s += __shfl_xor_sync(0xffffffffu, s, o);
        if (lane == 0) atomicAdd(accum, s);
    }
    __syncthreads();
}

__global__ void __launch_bounds__(TPB, 1)
emd_kernel(const float* __restrict__ preds, const float* __restrict__ gts,
           float* __restrict__ out, int out_size)
{
    extern __shared__ float sm[];
    float2* sGXY = (float2*)sm;
    float2* sPXY = (float2*)(sm + 2 * NN);
    float*  sGZ  = sm + 4 * NN;
    float*  sPZ  = sm + 5 * NN;
    float2* sZU  = (float2*)(sm + 6 * NN);
    float*  sPart = sm + 8 * NN;       // 256 floats; [248],[249] = act flags

    const int b       = blockIdx.x / CTAB;
    const int slot    = blockIdx.x % CTAB;
    const int colbase = slot * CPC;
    const int tid     = threadIdx.x;

    const float* gp = gts + (size_t)b * NN * 3;
    const float* pp = preds + (size_t)b * NN * 3;
    for (int i = tid; i < NN; i += TPB) {
        sGXY[i] = make_float2(gp[3 * i + 0], gp[3 * i + 1]);
        sGZ[i]  = gp[3 * i + 2];
        sPXY[i] = make_float2(pp[3 * i + 0], pp[3 * i + 1]);
        sPZ[i]  = pp[3 * i + 2];
    }
    __syncthreads();

    unsigned lb = 0;

    cham_pass(sGXY, sGZ, sPXY, sPZ, sPart, &g_s.cham[b], colbase);
    cham_pass(sPXY, sPZ, sGXY, sGZ, sPart, &g_s.cham[NB + b], colbase);

    float* AU1 = g_s.AU1 + b * NN;  float* BU1 = g_s.BU1 + b * NN;
    float* AU2 = g_s.AU2 + b * NN;  float* BU2 = g_s.BU2 + b * NN;
    const int off1 = 0, off2 = NITS_K * NB;

    // Interleaved Sinkhorn: run1 = C(gts,preds), run2 = C(preds,preds).
    // Independent loops share the barrier cadence; per-run act flags
    // reproduce each reference while_loop's exact iteration count.
    bool act1 = true, act2 = true;
    int it1 = 0, it2 = 0;
    while (act1 || act2) {
        // A-halves: sum over rows, write A (columns)
        if (act1)
            half_update(sGXY, sGZ, sPXY, sPZ, sZU, sPart, BU1, AU1,
                        &g_s.mvB[off1 + (it1 == 0 ? 0 : (it1 - 1) * NB) + b],
                        &g_s.mvA[off1 + it1 * NB + b],
                        &g_s.errA[off1 + it1 * NB + b],
                        it1 == 0, it1 == 0, colbase);
        if (act2)
            half_update(sPXY, sPZ, sPXY, sPZ, sZU, sPart, BU2, AU2,
                        &g_s.mvB[off2 + (it2 == 0 ? 0 : (it2 - 1) * NB) + b],
                        &g_s.mvA[off2 + it2 * NB + b],
                        &g_s.errA[off2 + it2 * NB + b],
                        it2 == 0, it2 == 0, colbase);
        grid_barrier(lb);
        // B-halves: sum over cols, write B (rows)
        if (act1)
            half_update(sPXY, sPZ, sGXY, sGZ, sZU, sPart, AU1, BU1,
                        &g_s.mvA[off1 + it1 * NB + b],
                        &g_s.mvB[off1 + it1 * NB + b],
                        &g_s.errB[off1 + it1 * NB + b],
                        false, it1 == 0, colbase);
        if (act2)
            half_update(sPXY, sPZ, sPXY, sPZ, sZU, sPart, AU2, BU2,
                        &g_s.mvA[off2 + it2 * NB + b],
                        &g_s.mvB[off2 + it2 * NB + b],
                        &g_s.errB[off2 + it2 * NB + b],
                        false, it2 == 0, colbase);
        grid_barrier(lb);

        // convergence check: thread0 only, broadcast via smem
        if (tid == 0) {
            float c1 = 0.f, c2 = 0.f;
            if (act1) {
                float ae = 0.f, be = 0.f;
#pragma unroll
                for (int bb = 0; bb < NB; bb++) {
                    ae = fmaxf(ae, __ldcg(&g_s.errA[off1 + it1 * NB + bb]));
                    be = fmaxf(be, __ldcg(&g_s.errB[off1 + it1 * NB + bb]));
                }
                ae *= (C_EPS / (float)NN); be *= (C_EPS / (float)NN);
                c1 = ((it1 + 1) < NITS_K && (ae >= C_TOL || be >= C_TOL)) ? 1.f : 0.f;
            }
            if (act2) {
                float ae = 0.f, be = 0.f;
#pragma unroll
                for (int bb = 0; bb < NB; bb++) {
                    ae = fmaxf(ae, __ldcg(&g_s.errA[off2 + it2 * NB + bb]));
                    be = fmaxf(be, __ldcg(&g_s.errB[off2 + it2 * NB + bb]));
                }
                ae *= (C_EPS / (float)NN); be *= (C_EPS / (float)NN);
                c2 = ((it2 + 1) < NITS_K && (ae >= C_TOL || be >= C_TOL)) ? 1.f : 0.f;
            }
            sPart[248] = c1; sPart[249] = c2;
        }
        __syncthreads();
        if (act1) { it1++; act1 = (sPart[248] != 0.f); }
        if (act2) { it2++; act2 = (sPart[249] != 0.f); }
        __syncthreads();
    }

    // cost passes on the final potentials
    cost_pass(sGXY, sGZ, sPXY, sPZ, sZU, sPart, BU1, AU1, &g_s.cost[b], colbase);
    cost_pass(sPXY, sPZ, sPXY, sPZ, sZU, sPart, BU2, AU2, &g_s.cost[NB + b], colbase);

    grid_barrier(lb);

    if (blockIdx.x == 0 && tid == 0) {
        const float inv_nm = 1.0f / ((float)NN * (float)NN);
        for (int bb = 0; bb < NB && bb < out_size; bb++) {
            float c1 = __ldcg(&g_s.cost[bb]);
            float c2 = __ldcg(&g_s.cost[NB + bb]);
            out[bb] = (c1 - 0.5f * c2) * inv_nm;
        }
        if (out_size >= 5) {
            float ch = 0.f;
            for (int bb = 0; bb < NB; bb++)
                ch += __ldcg(&g_s.cham[bb]) + __ldcg(&g_s.cham[NB + bb]);
            out[4] = ch / (float)(NB * NN);
        }
    }
}

extern "C" void kernel_launch(void* const* d_in, const int* in_sizes, int n_in,
                              void* d_out, int out_size)
{
    const float* preds = (const float*)d_in[0];
    const float* gts   = (const float*)d_in[1];
    float* out = (float*)d_out;

    void* sptr = nullptr;
    cudaGetSymbolAddress(&sptr, g_s);
    cudaMemsetAsync(sptr, 0, sizeof(ScratchT), 0);

    const int smem = (int)((8 * NN + 256) * sizeof(float));
    cudaFuncSetAttribute(emd_kernel, cudaFuncAttributeMaxDynamicSharedMemorySize, smem);
    emd_kernel<<<NCTA, TPB, smem, 0>>>(preds, gts, out, out_size);
}